// round 11
// baseline (speedup 1.0000x reference)
#include <cuda_runtime.h>
#include <cuda_bf16.h>
#include <cstdint>

#define NB 4
#define NH 6
#define NN 1024
#define ND 64
#define NCH 384
#define NPLANES (NB*NH)            /* 24 */
#define PLANE_QV (NN*ND)           /* 65536 */
#define S_TOTAL  (25165824u)       /* B*H*N*N */

// ---------------- scratch (device globals; no allocs allowed) ----------------
__device__ __nv_bfloat16 g_xh[NB*NN*NCH];          // x split  [m][k]
__device__ __nv_bfloat16 g_xl[NB*NN*NCH];
__device__ __nv_bfloat16 g_wqh[NCH*3*NCH];         // qkv_w^T split [n][k]
__device__ __nv_bfloat16 g_wql[NCH*3*NCH];
__device__ __nv_bfloat16 g_pwh[NCH*NCH];           // proj_w^T split [n][k]
__device__ __nv_bfloat16 g_pwl[NCH*NCH];
__device__ __nv_bfloat16 g_qh[NPLANES*PLANE_QV];   // q hi  [p][n][d]
__device__ __nv_bfloat16 g_ql[NPLANES*PLANE_QV];
__device__ __nv_bfloat16 g_kh[NPLANES*PLANE_QV];   // k hi  [p][m][d]
__device__ __nv_bfloat16 g_kl[NPLANES*PLANE_QV];
__device__ __nv_bfloat16 g_vh[NPLANES*PLANE_QV];   // v hi  [p][d][n]  (TRANSPOSED)
__device__ __nv_bfloat16 g_vl[NPLANES*PLANE_QV];
__device__ float g_qk[(size_t)NPLANES*NN*NN];      // raw scores f32
__device__ float2 g_g[S_TOTAL];                    // precomputed (g0,g1) gumbel draws
__device__ __nv_bfloat16 g_ah[(size_t)NPLANES*NN*NN];  // masked attn hi [p][n][m]
__device__ __nv_bfloat16 g_al[(size_t)NPLANES*NN*NN];
__device__ __nv_bfloat16 g_oh[NB*NN*NCH];          // attn@v result split [m][k]
__device__ __nv_bfloat16 g_ol[NB*NN*NCH];

// ---------------- threefry2x32-20 (host+device) ----------------
__host__ __device__ inline unsigned rotl32(unsigned x, int r){
#ifdef __CUDA_ARCH__
  return __funnelshift_l(x, x, r);
#else
  return (x << r) | (x >> (32 - r));
#endif
}

__host__ __device__ inline void threefry2x32(unsigned k0, unsigned k1,
                                             unsigned c0, unsigned c1,
                                             unsigned &o0, unsigned &o1){
  unsigned ks0 = k0, ks1 = k1, ks2 = k0 ^ k1 ^ 0x1BD11BDAu;
  unsigned x0 = c0 + ks0, x1 = c1 + ks1;
#define TF_RND(r) { x0 += x1; x1 = rotl32(x1, r); x1 ^= x0; }
  TF_RND(13) TF_RND(15) TF_RND(26) TF_RND(6)
  x0 += ks1; x1 += ks2 + 1u;
  TF_RND(17) TF_RND(29) TF_RND(16) TF_RND(24)
  x0 += ks2; x1 += ks0 + 2u;
  TF_RND(13) TF_RND(15) TF_RND(26) TF_RND(6)
  x0 += ks0; x1 += ks1 + 3u;
  TF_RND(17) TF_RND(29) TF_RND(16) TF_RND(24)
  x0 += ks1; x1 += ks2 + 4u;
  TF_RND(13) TF_RND(15) TF_RND(26) TF_RND(6)
  x0 += ks2; x1 += ks0 + 5u;
#undef TF_RND
  o0 = x0; o1 = x1;
}

__device__ __forceinline__ float gumbel_from_bits(unsigned bits){
  const float tiny = 1.17549435e-38f;
  float f = __uint_as_float((bits >> 9) | 0x3f800000u) - 1.0f;
  float r = fmaxf(tiny, f + tiny);
  return -__logf(-__logf(r));
}

// ---------------- bf16 split + mma helpers ----------------
__device__ __forceinline__ void f2bf(float x, __nv_bfloat16 &h, __nv_bfloat16 &l){
  h = __float2bfloat16(x);
  l = __float2bfloat16(x - __bfloat162float(h));
}
__device__ __forceinline__ unsigned packbf(__nv_bfloat16 a, __nv_bfloat16 b){
  unsigned short ua = __bfloat16_as_ushort(a), ub = __bfloat16_as_ushort(b);
  return (unsigned)ua | ((unsigned)ub << 16);
}

__device__ __forceinline__ uint32_t sptr(const void* p){
  return (uint32_t)__cvta_generic_to_shared(p);
}

__device__ __forceinline__ void ldm_x4(uint32_t a, uint32_t &r0, uint32_t &r1,
                                       uint32_t &r2, uint32_t &r3){
  asm volatile("ldmatrix.sync.aligned.m8n8.x4.shared.b16 {%0,%1,%2,%3}, [%4];"
    : "=r"(r0),"=r"(r1),"=r"(r2),"=r"(r3) : "r"(a));
}
__device__ __forceinline__ void mma16816(float &c0,float &c1,float &c2,float &c3,
    uint32_t a0,uint32_t a1,uint32_t a2,uint32_t a3, uint32_t b0,uint32_t b1){
  asm volatile("mma.sync.aligned.m16n8k16.row.col.f32.bf16.bf16.f32 "
    "{%0,%1,%2,%3}, {%4,%5,%6,%7}, {%8,%9}, {%0,%1,%2,%3};"
    : "+f"(c0),"+f"(c1),"+f"(c2),"+f"(c3)
    : "r"(a0),"r"(a1),"r"(a2),"r"(a3),"r"(b0),"r"(b1));
}

#define SQS 72

// Inner split-MMA step over one 64-col B strip (B via x4 ldmatrix, 2 n-octets/instr).
#define SPLIT_MMA_STEP(sBh_, sBl_, mh_, k0_, lane_, acc_, AH0,AH1,AH2,AH3, AL0,AL1,AL2,AL3) \
  { \
    const int _bq = (((lane_) >> 3) & 1) * 8; \
    const int _br = (((lane_) >> 4) & 1) * 8 + ((lane_) & 7); \
    _Pragma("unroll") \
    for (int _tp = 0; _tp < 2; _tp++){ \
      const int _row = (mh_) + _tp*16 + _br; \
      uint32_t _bh0,_bh1,_bh2,_bh3, _bl0,_bl1,_bl2,_bl3; \
      ldm_x4(sptr(&(sBh_)[_row*SQS + (k0_) + _bq]), _bh0,_bh1,_bh2,_bh3); \
      ldm_x4(sptr(&(sBl_)[_row*SQS + (k0_) + _bq]), _bl0,_bl1,_bl2,_bl3); \
      const int _t0 = _tp*2, _t1 = _tp*2 + 1; \
      mma16816(acc_[_t0][0],acc_[_t0][1],acc_[_t0][2],acc_[_t0][3], AH0,AH1,AH2,AH3, _bh0,_bh1); \
      mma16816(acc_[_t0][0],acc_[_t0][1],acc_[_t0][2],acc_[_t0][3], AH0,AH1,AH2,AH3, _bl0,_bl1); \
      mma16816(acc_[_t0][0],acc_[_t0][1],acc_[_t0][2],acc_[_t0][3], AL0,AL1,AL2,AL3, _bh0,_bh1); \
      mma16816(acc_[_t1][0],acc_[_t1][1],acc_[_t1][2],acc_[_t1][3], AH0,AH1,AH2,AH3, _bh2,_bh3); \
      mma16816(acc_[_t1][0],acc_[_t1][1],acc_[_t1][2],acc_[_t1][3], AH0,AH1,AH2,AH3, _bl2,_bl3); \
      mma16816(acc_[_t1][0],acc_[_t1][1],acc_[_t1][2],acc_[_t1][3], AL0,AL1,AL2,AL3, _bh2,_bh3); \
    } \
  }

// ---------------- K-GUMBEL: precompute (g0,g1) draws; depends only on keys ----------------
__global__ __launch_bounds__(256) void k_gumbel(unsigned k0a, unsigned k0b,
                                                unsigned k1a, unsigned k1b){
  const unsigned base = (blockIdx.x*256u + threadIdx.x)*4u;
  #pragma unroll
  for (int j=0;j<4;j++){
    unsigned idx = base + j;
    unsigned a0,a1,b0,b1;
    threefry2x32(k0a,k0b, 0u, idx, a0,a1);
    threefry2x32(k1a,k1b, 0u, idx, b0,b1);
    g_g[idx] = make_float2(gumbel_from_bits(a0 ^ a1), gumbel_from_bits(b0 ^ b1));
  }
}

// ---------------- K0a: split x into bf16 hi/lo ----------------
__global__ __launch_bounds__(256) void k_split_x(const float* __restrict__ X){
  const int i = blockIdx.x*256 + threadIdx.x;          // 393216 float4 groups
  float4 v = ((const float4*)X)[i];
  __nv_bfloat16 h0,l0,h1,l1,h2,l2,h3,l3;
  f2bf(v.x,h0,l0); f2bf(v.y,h1,l1); f2bf(v.z,h2,l2); f2bf(v.w,h3,l3);
  ((uint2*)g_xh)[i] = make_uint2(packbf(h0,h1), packbf(h2,h3));
  ((uint2*)g_xl)[i] = make_uint2(packbf(l0,l1), packbf(l2,l3));
}

// ---------------- K0b: transpose-split weight [R][C] f32 -> [C][R] bf16 hi/lo ----------------
__global__ void k_tsplit(const float* __restrict__ W,
                         __nv_bfloat16* __restrict__ oh,
                         __nv_bfloat16* __restrict__ ol,
                         int R, int C){
  __shared__ float t[32][33];
  const int tx = threadIdx.x, ty = threadIdx.y;       // 32 x 8
  const int c0 = blockIdx.x*32, r0 = blockIdx.y*32;
  #pragma unroll
  for (int j=0;j<4;j++) t[ty+8*j][tx] = W[(size_t)(r0+ty+8*j)*C + c0 + tx];
  __syncthreads();
  #pragma unroll
  for (int j=0;j<4;j++){
    float v = t[tx][ty+8*j];
    __nv_bfloat16 h,l; f2bf(v,h,l);
    size_t o = (size_t)(c0+ty+8*j)*R + r0 + tx;
    oh[o] = h; ol[o] = l;
  }
}

// ---------------- K1: qkv = x @ W + b via mma, scatter to q/k/v hi-lo ----------------
__global__ __launch_bounds__(256) void k_qkv_mma(const float* __restrict__ bias){
  __shared__ __align__(16) __nv_bfloat16 sAh[64*SQS], sAl[64*SQS];
  __shared__ __align__(16) __nv_bfloat16 sBh[64*SQS], sBl[64*SQS];
  __shared__ __align__(16) float sT[64][65];
  const int tid = threadIdx.x;
  const int n0 = blockIdx.x * 64;      // 0..1151
  const int m0 = blockIdx.y * 64;      // 0..4095
  const int w = tid >> 5, lane = tid & 31;
  const int ns = (w >> 1) * 16, mh = (w & 1) * 32;
  const int crow = tid >> 3, ccol = (tid & 7) * 8;
  float acc[4][4] = {};
  for (int kb = 0; kb < 384; kb += 64){
    #pragma unroll
    for (int c0=0;c0<2;c0++){
      int row = crow + 32*c0;
      *(uint4*)&sAh[row*SQS+ccol] = *(const uint4*)&g_xh[(size_t)(m0+row)*384 + kb + ccol];
      *(uint4*)&sAl[row*SQS+ccol] = *(const uint4*)&g_xl[(size_t)(m0+row)*384 + kb + ccol];
      *(uint4*)&sBh[row*SQS+ccol] = *(const uint4*)&g_wqh[(size_t)(n0+row)*384 + kb + ccol];
      *(uint4*)&sBl[row*SQS+ccol] = *(const uint4*)&g_wql[(size_t)(n0+row)*384 + kb + ccol];
    }
    __syncthreads();
    #pragma unroll
    for (int ks=0; ks<4; ks++){
      const int k0 = ks*16;
      const int arow = ns + (lane & 15);
      const int acol = k0 + (lane >> 4) * 8;
      uint32_t ah0,ah1,ah2,ah3, al0,al1,al2,al3;
      ldm_x4(sptr(&sAh[arow*SQS + acol]), ah0,ah1,ah2,ah3);
      ldm_x4(sptr(&sAl[arow*SQS + acol]), al0,al1,al2,al3);
      SPLIT_MMA_STEP(sBh, sBl, mh, k0, lane, acc, ah0,ah1,ah2,ah3, al0,al1,al2,al3)
    }
    __syncthreads();
  }
  const int s = n0 / 384;
  const int h = (n0 % 384) / 64;
  if (s < 2){
    __nv_bfloat16* dh = s ? g_kh : g_qh;
    __nv_bfloat16* dl = s ? g_kl : g_ql;
    const int rl = m0 + ns + (lane >> 2);
    #pragma unroll
    for (int t=0;t<4;t++){
      const int col = mh + t*8 + (lane & 3)*2;
      const float b0 = bias[n0+col], b1 = bias[n0+col+1];
      #pragma unroll
      for (int half=0; half<2; half++){
        int r = rl + 8*half;
        int bb = r >> 10, nn = r & 1023;
        size_t base = ((size_t)(bb*NH + h)*NN + nn)*ND + col;
        __nv_bfloat16 h0,l0,h1,l1;
        f2bf(acc[t][2*half+0]+b0, h0,l0);
        f2bf(acc[t][2*half+1]+b1, h1,l1);
        *(unsigned*)&dh[base] = packbf(h0,h1);
        *(unsigned*)&dl[base] = packbf(l0,l1);
      }
    }
  } else {
    const int rl = ns + (lane >> 2);
    #pragma unroll
    for (int t=0;t<4;t++){
      const int col = mh + t*8 + (lane & 3)*2;
      const float b0 = bias[n0+col], b1 = bias[n0+col+1];
      sT[col  ][rl  ] = acc[t][0]+b0;
      sT[col+1][rl  ] = acc[t][1]+b1;
      sT[col  ][rl+8] = acc[t][2]+b0;
      sT[col+1][rl+8] = acc[t][3]+b1;
    }
    __syncthreads();
    const int dloc = tid >> 2;
    const int nch  = (tid & 3) * 16;
    const int bb = m0 >> 10;
    const int nb = (m0 & 1023) + nch;
    size_t base = ((size_t)(bb*NH + h))*PLANE_QV + (size_t)dloc*NN + nb;
    union { __nv_bfloat16 q[16]; uint4 u[2]; } ph, pl;
    #pragma unroll
    for (int kk=0;kk<16;kk++) f2bf(sT[dloc][nch+kk], ph.q[kk], pl.q[kk]);
    *(uint4*)&g_vh[base]   = ph.u[0];
    *(uint4*)&g_vh[base+8] = ph.u[1];
    *(uint4*)&g_vl[base]   = pl.u[0];
    *(uint4*)&g_vl[base+8] = pl.u[1];
  }
}

// ---------------- K2: scores via mma.sync bf16 split ----------------
__global__ __launch_bounds__(256) void k_scores_mma(){
  __shared__ __align__(16) __nv_bfloat16 sQh[64*SQS], sQl[64*SQS];
  __shared__ __align__(16) __nv_bfloat16 sKh[64*SQS], sKl[64*SQS];
  const int tid = threadIdx.x;
  const int p = blockIdx.z, n0 = blockIdx.y*64, m0 = blockIdx.x*64;
  const __nv_bfloat16* Qh = g_qh + (size_t)p*PLANE_QV + (size_t)n0*ND;
  const __nv_bfloat16* Ql = g_ql + (size_t)p*PLANE_QV + (size_t)n0*ND;
  const __nv_bfloat16* Kh = g_kh + (size_t)p*PLANE_QV + (size_t)m0*ND;
  const __nv_bfloat16* Kl = g_kl + (size_t)p*PLANE_QV + (size_t)m0*ND;
  #pragma unroll
  for (int c0=0;c0<2;c0++){
    int c = tid + 256*c0;
    int row = c >> 3, col = (c & 7) * 8;
    *(uint4*)&sQh[row*SQS+col] = *(const uint4*)&Qh[row*64+col];
    *(uint4*)&sQl[row*SQS+col] = *(const uint4*)&Ql[row*64+col];
    *(uint4*)&sKh[row*SQS+col] = *(const uint4*)&Kh[row*64+col];
    *(uint4*)&sKl[row*SQS+col] = *(const uint4*)&Kl[row*64+col];
  }
  __syncthreads();
  const int w = tid >> 5, lane = tid & 31;
  const int ns = (w >> 1) * 16, mh = (w & 1) * 32;
  float acc[4][4] = {};
  #pragma unroll
  for (int ks=0; ks<4; ks++){
    const int k0 = ks*16;
    const int arow = ns + (lane & 15);
    const int acol = k0 + (lane >> 4) * 8;
    uint32_t ah0,ah1,ah2,ah3, al0,al1,al2,al3;
    ldm_x4(sptr(&sQh[arow*SQS + acol]), ah0,ah1,ah2,ah3);
    ldm_x4(sptr(&sQl[arow*SQS + acol]), al0,al1,al2,al3);
    SPLIT_MMA_STEP(sKh, sKl, mh, k0, lane, acc, ah0,ah1,ah2,ah3, al0,al1,al2,al3)
  }
  const int crow = n0 + ns + (lane >> 2);
  #pragma unroll
  for (int t=0;t<4;t++){
    const int ccol = m0 + mh + t*8 + (lane & 3)*2;
    size_t base = ((size_t)p<<20) + ((size_t)crow<<10) + ccol;
    *(float2*)&g_qk[base]            = make_float2(acc[t][0], acc[t][1]);
    *(float2*)&g_qk[base + (8<<10)]  = make_float2(acc[t][2], acc[t][3]);
  }
}

// ---------------- K3: fused softmax + conv/tanh + mask (gumbel preloaded) ----------------
__global__ __launch_bounds__(256) void k_smix(const float* __restrict__ cw,
                                              const float* __restrict__ cb,
                                              float* __restrict__ am_out,
                                              float* __restrict__ u_out){
  __shared__ float scw[36];
  __shared__ float scb[6];
  __shared__ float red[6][8];
  __shared__ float bcast[6];
  const int tid = threadIdx.x;
  const int wid = tid >> 5, lane = tid & 31;
  if (tid < 36) scw[tid] = cw[tid];
  if (tid < 6)  scb[tid] = cb[tid];
  const int n = blockIdx.x;
  const int b = blockIdx.y;
  float qv[6][4];
  #pragma unroll
  for (int h=0;h<6;h++){
    size_t base = ((size_t)(b*6+h) << 20) + ((size_t)n << 10) + tid;
    #pragma unroll
    for (int j=0;j<4;j++) qv[h][j] = g_qk[base + 256*j];
  }
  #pragma unroll
  for (int h=0;h<6;h++){
    float lm = fmaxf(fmaxf(qv[h][0],qv[h][1]), fmaxf(qv[h][2],qv[h][3]));
    #pragma unroll
    for (int o=16;o>0;o>>=1) lm = fmaxf(lm, __shfl_xor_sync(0xffffffffu, lm, o));
    if (lane == 0) red[h][wid] = lm;
  }
  __syncthreads();
  if (tid < 6){
    float mm = red[tid][0];
    #pragma unroll
    for (int i=1;i<8;i++) mm = fmaxf(mm, red[tid][i]);
    bcast[tid] = mm;
  }
  __syncthreads();
  float at[6][4];
  #pragma unroll
  for (int h=0;h<6;h++){
    float mr = bcast[h];
    float s = 0.f;
    #pragma unroll
    for (int j=0;j<4;j++){ at[h][j] = __expf((qv[h][j]-mr)*0.125f); s += at[h][j]; }
    #pragma unroll
    for (int o=16;o>0;o>>=1) s += __shfl_xor_sync(0xffffffffu, s, o);
    if (lane == 0) red[h][wid] = s;
  }
  __syncthreads();
  if (tid < 6){
    float ss = red[tid][0];
    #pragma unroll
    for (int i=1;i<8;i++) ss += red[tid][i];
    bcast[tid] = ss;
  }
  __syncthreads();
  #pragma unroll
  for (int h=0;h<6;h++){
    float inv = 1.0f / bcast[h];
    size_t base = ((size_t)(b*6+h) << 20) + ((size_t)n << 10) + tid;
    #pragma unroll
    for (int j=0;j<4;j++){
      at[h][j] *= inv;
      am_out[base + 256*j] = at[h][j];
    }
  }
  #pragma unroll
  for (int o=0;o<6;o++){
    #pragma unroll
    for (int j=0;j<4;j++){
      float t = scb[o];
      #pragma unroll
      for (int h=0;h<6;h++) t = fmaf(scw[o*6+h], qv[h][j], t);
      float u = (tanhf(t) + 1.0f) * 0.5f;
      unsigned idx = ((unsigned)(b*6+o) << 20) | ((unsigned)n << 10) | (unsigned)(tid + 256*j);
      u_out[idx] = u;
      float2 g = g_g[idx];
      bool hard = ((1.0f - u) + g.y) > (u + g.x);
      float masked = hard ? at[o][j] : 0.0f;
      __nv_bfloat16 mh, ml;
      f2bf(masked, mh, ml);
      g_ah[idx] = mh;
      g_al[idx] = ml;
    }
  }
}

// ---------------- K4: attn @ v via mma -> bf16 hi/lo for proj ----------------
__global__ __launch_bounds__(256) void k_attnv_mma(){
  __shared__ __align__(16) __nv_bfloat16 sAh[64*SQS], sAl[64*SQS];
  __shared__ __align__(16) __nv_bfloat16 sVh[64*SQS], sVl[64*SQS];
  const int tid = threadIdx.x;
  const int p = blockIdx.y, n0 = blockIdx.x*64;
  const __nv_bfloat16* Ah = g_ah + ((((size_t)p<<10) + n0) << 10);
  const __nv_bfloat16* Al = g_al + ((((size_t)p<<10) + n0) << 10);
  const __nv_bfloat16* Vh = g_vh + (size_t)p*PLANE_QV;
  const __nv_bfloat16* Vl = g_vl + (size_t)p*PLANE_QV;
  const int w = tid >> 5, lane = tid & 31;
  const int ns = (w >> 1) * 16, dh = (w & 1) * 32;
  float acc[4][4] = {};
  const int crow = tid >> 3, ccol = (tid & 7) * 8;
  for (int mb = 0; mb < 1024; mb += 64){
    #pragma unroll
    for (int c0=0;c0<2;c0++){
      int row = crow + 32*c0;
      *(uint4*)&sAh[row*SQS+ccol] = *(const uint4*)&Ah[(size_t)row*1024 + mb + ccol];
      *(uint4*)&sAl[row*SQS+ccol] = *(const uint4*)&Al[(size_t)row*1024 + mb + ccol];
      *(uint4*)&sVh[row*SQS+ccol] = *(const uint4*)&Vh[(size_t)row*1024 + mb + ccol];
      *(uint4*)&sVl[row*SQS+ccol] = *(const uint4*)&Vl[(size_t)row*1024 + mb + ccol];
    }
    __syncthreads();
    #pragma unroll
    for (int ks=0; ks<4; ks++){
      const int k0 = ks*16;
      const int arow = ns + (lane & 15);
      const int acol = k0 + (lane >> 4) * 8;
      uint32_t ah0,ah1,ah2,ah3, al0,al1,al2,al3;
      ldm_x4(sptr(&sAh[arow*SQS + acol]), ah0,ah1,ah2,ah3);
      ldm_x4(sptr(&sAl[arow*SQS + acol]), al0,al1,al2,al3);
      SPLIT_MMA_STEP(sVh, sVl, dh, k0, lane, acc, ah0,ah1,ah2,ah3, al0,al1,al2,al3)
    }
    __syncthreads();
  }
  const int bb = p / 6, hh = p % 6;
  const int orow = n0 + ns + (lane >> 2);
  #pragma unroll
  for (int t=0;t<4;t++){
    const int ocol = hh*64 + dh + t*8 + (lane & 3)*2;
    #pragma unroll
    for (int half=0; half<2; half++){
      size_t base = (size_t)(bb*NN + orow + 8*half)*NCH + ocol;
      __nv_bfloat16 h0,l0,h1,l1;
      f2bf(acc[t][2*half+0], h0,l0);
      f2bf(acc[t][2*half+1], h1,l1);
      *(unsigned*)&g_oh[base] = packbf(h0,h1);
      *(unsigned*)&g_ol[base] = packbf(l0,l1);
    }
  }
}

// ---------------- K5: out = o @ proj_w + proj_b via mma ----------------
__global__ __launch_bounds__(256) void k_proj_mma(const float* __restrict__ bias,
                                                  float* __restrict__ out){
  __shared__ __align__(16) __nv_bfloat16 sAh[64*SQS], sAl[64*SQS];
  __shared__ __align__(16) __nv_bfloat16 sBh[64*SQS], sBl[64*SQS];
  const int tid = threadIdx.x;
  const int n0 = blockIdx.x * 64;      // 0..383
  const int m0 = blockIdx.y * 64;      // 0..4095
  const int w = tid >> 5, lane = tid & 31;
  const int ns = (w >> 1) * 16, mh = (w & 1) * 32;
  const int crow = tid >> 3, ccol = (tid & 7) * 8;
  float acc[4][4] = {};
  for (int kb = 0; kb < 384; kb += 64){
    #pragma unroll
    for (int c0=0;c0<2;c0++){
      int row = crow + 32*c0;
      *(uint4*)&sAh[row*SQS+ccol] = *(const uint4*)&g_oh[(size_t)(m0+row)*384 + kb + ccol];
      *(uint4*)&sAl[row*SQS+ccol] = *(const uint4*)&g_ol[(size_t)(m0+row)*384 + kb + ccol];
      *(uint4*)&sBh[row*SQS+ccol] = *(const uint4*)&g_pwh[(size_t)(n0+row)*384 + kb + ccol];
      *(uint4*)&sBl[row*SQS+ccol] = *(const uint4*)&g_pwl[(size_t)(n0+row)*384 + kb + ccol];
    }
    __syncthreads();
    #pragma unroll
    for (int ks=0; ks<4; ks++){
      const int k0 = ks*16;
      const int arow = ns + (lane & 15);
      const int acol = k0 + (lane >> 4) * 8;
      uint32_t ah0,ah1,ah2,ah3, al0,al1,al2,al3;
      ldm_x4(sptr(&sAh[arow*SQS + acol]), ah0,ah1,ah2,ah3);
      ldm_x4(sptr(&sAl[arow*SQS + acol]), al0,al1,al2,al3);
      SPLIT_MMA_STEP(sBh, sBl, mh, k0, lane, acc, ah0,ah1,ah2,ah3, al0,al1,al2,al3)
    }
    __syncthreads();
  }
  const int rl = m0 + ns + (lane >> 2);
  #pragma unroll
  for (int t=0;t<4;t++){
    const int col = n0 + mh + t*8 + (lane & 3)*2;
    const float b0 = bias[col], b1 = bias[col+1];
    *(float2*)&out[(size_t)rl*384 + col]     = make_float2(acc[t][0]+b0, acc[t][1]+b1);
    *(float2*)&out[(size_t)(rl+8)*384 + col] = make_float2(acc[t][2]+b0, acc[t][3]+b1);
  }
}

// ---------------- launch ----------------
extern "C" void kernel_launch(void* const* d_in, const int* in_sizes, int n_in,
                              void* d_out, int out_size){
  (void)in_sizes; (void)n_in; (void)out_size;
  const float* x      = (const float*)d_in[0];
  const float* qkv_w  = (const float*)d_in[1];
  const float* qkv_b  = (const float*)d_in[2];
  const float* proj_w = (const float*)d_in[3];
  const float* proj_b = (const float*)d_in[4];
  const float* conv_w = (const float*)d_in[5];
  const float* conv_b = (const float*)d_in[6];
  float* out      = (float*)d_out;
  float* out_attn = out + (size_t)NB*NN*NCH;          // 1,572,864
  float* out_u    = out_attn + (size_t)S_TOTAL;       // +25,165,824

  unsigned k0a,k0b,k1a,k1b;
  threefry2x32(0u, 42u, 0u, 0u, k0a, k0b);
  threefry2x32(0u, 42u, 0u, 1u, k1a, k1b);

  __nv_bfloat16 *wqh_p, *wql_p, *pwh_p, *pwl_p;
  cudaGetSymbolAddress((void**)&wqh_p, g_wqh);
  cudaGetSymbolAddress((void**)&wql_p, g_wql);
  cudaGetSymbolAddress((void**)&pwh_p, g_pwh);
  cudaGetSymbolAddress((void**)&pwl_p, g_pwl);

  // lazy-init side stream + events (created on the first (correctness) call,
  // outside graph capture; reused identically every call)
  static cudaStream_t s2 = nullptr;
  static cudaEvent_t evFork = nullptr, evJoin = nullptr;
  if (s2 == nullptr){
    cudaStreamCreateWithFlags(&s2, cudaStreamNonBlocking);
    cudaEventCreateWithFlags(&evFork, cudaEventDisableTiming);
    cudaEventCreateWithFlags(&evJoin, cudaEventDisableTiming);
  }

  // fork: gumbel precompute (input-independent) runs concurrent with qkv+scores
  cudaEventRecord(evFork, 0);
  cudaStreamWaitEvent(s2, evFork, 0);
  k_gumbel    <<<24576, 256, 0, s2>>>(k0a,k0b,k1a,k1b);
  cudaEventRecord(evJoin, s2);

  k_split_x   <<<1536, 256>>>(x);
  k_tsplit    <<<dim3(36,12), dim3(32,8)>>>(qkv_w, wqh_p, wql_p, 384, 1152);
  k_tsplit    <<<dim3(12,12), dim3(32,8)>>>(proj_w, pwh_p, pwl_p, 384, 384);
  k_qkv_mma   <<<dim3(18,64),   256>>>(qkv_b);
  k_scores_mma<<<dim3(16,16,24),256>>>();

  // join: smix needs g_g
  cudaStreamWaitEvent(0, evJoin, 0);
  k_smix      <<<dim3(1024,4),  256>>>(conv_w, conv_b, out_attn, out_u);
  k_attnv_mma <<<dim3(16,24),   256>>>();
  k_proj_mma  <<<dim3(6,64),    256>>>(proj_b, out);
}

// round 14
// speedup vs baseline: 1.5171x; 1.5171x over previous
#include <cuda_runtime.h>
#include <cuda_bf16.h>
#include <cstdint>

#define NB 4
#define NH 6
#define NN 1024
#define ND 64
#define NCH 384
#define NPLANES (NB*NH)            /* 24 */
#define PLANE_QV (NN*ND)           /* 65536 */
#define S_TOTAL  (25165824u)       /* B*H*N*N */

// ---------------- scratch (device globals; no allocs allowed) ----------------
__device__ __nv_bfloat16 g_xh[NB*NN*NCH];          // x split  [m][k]
__device__ __nv_bfloat16 g_xl[NB*NN*NCH];
__device__ __nv_bfloat16 g_wqh[NCH*3*NCH];         // qkv_w^T split [n][k]
__device__ __nv_bfloat16 g_wql[NCH*3*NCH];
__device__ __nv_bfloat16 g_pwh[NCH*NCH];           // proj_w^T split [n][k]
__device__ __nv_bfloat16 g_pwl[NCH*NCH];
__device__ __nv_bfloat16 g_qh[NPLANES*PLANE_QV];   // q hi  [p][n][d]
__device__ __nv_bfloat16 g_ql[NPLANES*PLANE_QV];
__device__ __nv_bfloat16 g_kh[NPLANES*PLANE_QV];   // k hi  [p][m][d]
__device__ __nv_bfloat16 g_kl[NPLANES*PLANE_QV];
__device__ __nv_bfloat16 g_vh[NPLANES*PLANE_QV];   // v hi  [p][d][n]  (TRANSPOSED)
__device__ __nv_bfloat16 g_vl[NPLANES*PLANE_QV];
__device__ float g_qk[(size_t)NPLANES*NN*NN];      // raw scores f32
__device__ __nv_bfloat16 g_ah[(size_t)NPLANES*NN*NN];  // masked attn hi [p][n][m]
__device__ __nv_bfloat16 g_al[(size_t)NPLANES*NN*NN];  // masked attn lo
__device__ __nv_bfloat16 g_oh[NB*NN*NCH];          // attn@v result split [m][k]
__device__ __nv_bfloat16 g_ol[NB*NN*NCH];

// ---------------- threefry2x32-20 (host+device) ----------------
__host__ __device__ inline unsigned rotl32(unsigned x, int r){
#ifdef __CUDA_ARCH__
  return __funnelshift_l(x, x, r);
#else
  return (x << r) | (x >> (32 - r));
#endif
}

__host__ __device__ inline void threefry2x32(unsigned k0, unsigned k1,
                                             unsigned c0, unsigned c1,
                                             unsigned &o0, unsigned &o1){
  unsigned ks0 = k0, ks1 = k1, ks2 = k0 ^ k1 ^ 0x1BD11BDAu;
  unsigned x0 = c0 + ks0, x1 = c1 + ks1;
#define TF_RND(r) { x0 += x1; x1 = rotl32(x1, r); x1 ^= x0; }
  TF_RND(13) TF_RND(15) TF_RND(26) TF_RND(6)
  x0 += ks1; x1 += ks2 + 1u;
  TF_RND(17) TF_RND(29) TF_RND(16) TF_RND(24)
  x0 += ks2; x1 += ks0 + 2u;
  TF_RND(13) TF_RND(15) TF_RND(26) TF_RND(6)
  x0 += ks0; x1 += ks1 + 3u;
  TF_RND(17) TF_RND(29) TF_RND(16) TF_RND(24)
  x0 += ks1; x1 += ks2 + 4u;
  TF_RND(13) TF_RND(15) TF_RND(26) TF_RND(6)
  x0 += ks2; x1 += ks0 + 5u;
#undef TF_RND
  o0 = x0; o1 = x1;
}

__device__ __forceinline__ float gumbel_from_bits(unsigned bits){
  const float tiny = 1.17549435e-38f;
  float f = __uint_as_float((bits >> 9) | 0x3f800000u) - 1.0f;
  float r = fmaxf(tiny, f + tiny);
  return -__logf(-__logf(r));
}

// ---------------- bf16 split + mma helpers ----------------
__device__ __forceinline__ void f2bf(float x, __nv_bfloat16 &h, __nv_bfloat16 &l){
  h = __float2bfloat16(x);
  l = __float2bfloat16(x - __bfloat162float(h));
}
__device__ __forceinline__ unsigned packbf(__nv_bfloat16 a, __nv_bfloat16 b){
  unsigned short ua = __bfloat16_as_ushort(a), ub = __bfloat16_as_ushort(b);
  return (unsigned)ua | ((unsigned)ub << 16);
}

__device__ __forceinline__ uint32_t sptr(const void* p){
  return (uint32_t)__cvta_generic_to_shared(p);
}

__device__ __forceinline__ void ldm_x4(uint32_t a, uint32_t &r0, uint32_t &r1,
                                       uint32_t &r2, uint32_t &r3){
  asm volatile("ldmatrix.sync.aligned.m8n8.x4.shared.b16 {%0,%1,%2,%3}, [%4];"
    : "=r"(r0),"=r"(r1),"=r"(r2),"=r"(r3) : "r"(a));
}
__device__ __forceinline__ void mma16816(float &c0,float &c1,float &c2,float &c3,
    uint32_t a0,uint32_t a1,uint32_t a2,uint32_t a3, uint32_t b0,uint32_t b1){
  asm volatile("mma.sync.aligned.m16n8k16.row.col.f32.bf16.bf16.f32 "
    "{%0,%1,%2,%3}, {%4,%5,%6,%7}, {%8,%9}, {%0,%1,%2,%3};"
    : "+f"(c0),"+f"(c1),"+f"(c2),"+f"(c3)
    : "r"(a0),"r"(a1),"r"(a2),"r"(a3),"r"(b0),"r"(b1));
}

#define SQS 72

// Inner split-MMA step over one 64-col B strip (B via x4 ldmatrix, 2 n-octets/instr).
#define SPLIT_MMA_STEP(sBh_, sBl_, mh_, k0_, lane_, acc_, AH0,AH1,AH2,AH3, AL0,AL1,AL2,AL3) \
  { \
    const int _bq = (((lane_) >> 3) & 1) * 8; \
    const int _br = (((lane_) >> 4) & 1) * 8 + ((lane_) & 7); \
    _Pragma("unroll") \
    for (int _tp = 0; _tp < 2; _tp++){ \
      const int _row = (mh_) + _tp*16 + _br; \
      uint32_t _bh0,_bh1,_bh2,_bh3, _bl0,_bl1,_bl2,_bl3; \
      ldm_x4(sptr(&(sBh_)[_row*SQS + (k0_) + _bq]), _bh0,_bh1,_bh2,_bh3); \
      ldm_x4(sptr(&(sBl_)[_row*SQS + (k0_) + _bq]), _bl0,_bl1,_bl2,_bl3); \
      const int _t0 = _tp*2, _t1 = _tp*2 + 1; \
      mma16816(acc_[_t0][0],acc_[_t0][1],acc_[_t0][2],acc_[_t0][3], AH0,AH1,AH2,AH3, _bh0,_bh1); \
      mma16816(acc_[_t0][0],acc_[_t0][1],acc_[_t0][2],acc_[_t0][3], AH0,AH1,AH2,AH3, _bl0,_bl1); \
      mma16816(acc_[_t0][0],acc_[_t0][1],acc_[_t0][2],acc_[_t0][3], AL0,AL1,AL2,AL3, _bh0,_bh1); \
      mma16816(acc_[_t1][0],acc_[_t1][1],acc_[_t1][2],acc_[_t1][3], AH0,AH1,AH2,AH3, _bh2,_bh3); \
      mma16816(acc_[_t1][0],acc_[_t1][1],acc_[_t1][2],acc_[_t1][3], AH0,AH1,AH2,AH3, _bl2,_bl3); \
      mma16816(acc_[_t1][0],acc_[_t1][1],acc_[_t1][2],acc_[_t1][3], AL0,AL1,AL2,AL3, _bh2,_bh3); \
    } \
  }

// ---------------- K0a: split x into bf16 hi/lo ----------------
__global__ __launch_bounds__(256) void k_split_x(const float* __restrict__ X){
  const int i = blockIdx.x*256 + threadIdx.x;          // 393216 float4 groups
  float4 v = ((const float4*)X)[i];
  __nv_bfloat16 h0,l0,h1,l1,h2,l2,h3,l3;
  f2bf(v.x,h0,l0); f2bf(v.y,h1,l1); f2bf(v.z,h2,l2); f2bf(v.w,h3,l3);
  ((uint2*)g_xh)[i] = make_uint2(packbf(h0,h1), packbf(h2,h3));
  ((uint2*)g_xl)[i] = make_uint2(packbf(l0,l1), packbf(l2,l3));
}

// ---------------- K0b: transpose-split weight [R][C] f32 -> [C][R] bf16 hi/lo ----------------
__global__ void k_tsplit(const float* __restrict__ W,
                         __nv_bfloat16* __restrict__ oh,
                         __nv_bfloat16* __restrict__ ol,
                         int R, int C){
  __shared__ float t[32][33];
  const int tx = threadIdx.x, ty = threadIdx.y;       // 32 x 8
  const int c0 = blockIdx.x*32, r0 = blockIdx.y*32;
  #pragma unroll
  for (int j=0;j<4;j++) t[ty+8*j][tx] = W[(size_t)(r0+ty+8*j)*C + c0 + tx];
  __syncthreads();
  #pragma unroll
  for (int j=0;j<4;j++){
    float v = t[tx][ty+8*j];
    __nv_bfloat16 h,l; f2bf(v,h,l);
    size_t o = (size_t)(c0+ty+8*j)*R + r0 + tx;
    oh[o] = h; ol[o] = l;
  }
}

// ---------------- K1: qkv = x @ W + b via mma, scatter to q/k/v hi-lo ----------------
__global__ __launch_bounds__(256) void k_qkv_mma(const float* __restrict__ bias){
  __shared__ __align__(16) __nv_bfloat16 sAh[64*SQS], sAl[64*SQS];
  __shared__ __align__(16) __nv_bfloat16 sBh[64*SQS], sBl[64*SQS];
  __shared__ __align__(16) float sT[64][65];
  const int tid = threadIdx.x;
  const int n0 = blockIdx.x * 64;      // 0..1151
  const int m0 = blockIdx.y * 64;      // 0..4095
  const int w = tid >> 5, lane = tid & 31;
  const int ns = (w >> 1) * 16, mh = (w & 1) * 32;
  const int crow = tid >> 3, ccol = (tid & 7) * 8;
  float acc[4][4] = {};
  for (int kb = 0; kb < 384; kb += 64){
    #pragma unroll
    for (int c0=0;c0<2;c0++){
      int row = crow + 32*c0;
      *(uint4*)&sAh[row*SQS+ccol] = *(const uint4*)&g_xh[(size_t)(m0+row)*384 + kb + ccol];
      *(uint4*)&sAl[row*SQS+ccol] = *(const uint4*)&g_xl[(size_t)(m0+row)*384 + kb + ccol];
      *(uint4*)&sBh[row*SQS+ccol] = *(const uint4*)&g_wqh[(size_t)(n0+row)*384 + kb + ccol];
      *(uint4*)&sBl[row*SQS+ccol] = *(const uint4*)&g_wql[(size_t)(n0+row)*384 + kb + ccol];
    }
    __syncthreads();
    #pragma unroll
    for (int ks=0; ks<4; ks++){
      const int k0 = ks*16;
      const int arow = ns + (lane & 15);
      const int acol = k0 + (lane >> 4) * 8;
      uint32_t ah0,ah1,ah2,ah3, al0,al1,al2,al3;
      ldm_x4(sptr(&sAh[arow*SQS + acol]), ah0,ah1,ah2,ah3);
      ldm_x4(sptr(&sAl[arow*SQS + acol]), al0,al1,al2,al3);
      SPLIT_MMA_STEP(sBh, sBl, mh, k0, lane, acc, ah0,ah1,ah2,ah3, al0,al1,al2,al3)
    }
    __syncthreads();
  }
  const int s = n0 / 384;
  const int h = (n0 % 384) / 64;
  if (s < 2){
    __nv_bfloat16* dh = s ? g_kh : g_qh;
    __nv_bfloat16* dl = s ? g_kl : g_ql;
    const int rl = m0 + ns + (lane >> 2);
    #pragma unroll
    for (int t=0;t<4;t++){
      const int col = mh + t*8 + (lane & 3)*2;
      const float b0 = bias[n0+col], b1 = bias[n0+col+1];
      #pragma unroll
      for (int half=0; half<2; half++){
        int r = rl + 8*half;
        int bb = r >> 10, nn = r & 1023;
        size_t base = ((size_t)(bb*NH + h)*NN + nn)*ND + col;
        __nv_bfloat16 h0,l0,h1,l1;
        f2bf(acc[t][2*half+0]+b0, h0,l0);
        f2bf(acc[t][2*half+1]+b1, h1,l1);
        *(unsigned*)&dh[base] = packbf(h0,h1);
        *(unsigned*)&dl[base] = packbf(l0,l1);
      }
    }
  } else {
    const int rl = ns + (lane >> 2);
    #pragma unroll
    for (int t=0;t<4;t++){
      const int col = mh + t*8 + (lane & 3)*2;
      const float b0 = bias[n0+col], b1 = bias[n0+col+1];
      sT[col  ][rl  ] = acc[t][0]+b0;
      sT[col+1][rl  ] = acc[t][1]+b1;
      sT[col  ][rl+8] = acc[t][2]+b0;
      sT[col+1][rl+8] = acc[t][3]+b1;
    }
    __syncthreads();
    const int dloc = tid >> 2;
    const int nch  = (tid & 3) * 16;
    const int bb = m0 >> 10;
    const int nb = (m0 & 1023) + nch;
    size_t base = ((size_t)(bb*NH + h))*PLANE_QV + (size_t)dloc*NN + nb;
    union { __nv_bfloat16 q[16]; uint4 u[2]; } ph, pl;
    #pragma unroll
    for (int kk=0;kk<16;kk++) f2bf(sT[dloc][nch+kk], ph.q[kk], pl.q[kk]);
    *(uint4*)&g_vh[base]   = ph.u[0];
    *(uint4*)&g_vh[base+8] = ph.u[1];
    *(uint4*)&g_vl[base]   = pl.u[0];
    *(uint4*)&g_vl[base+8] = pl.u[1];
  }
}

// ---------------- K2: scores via mma.sync bf16 split ----------------
__global__ __launch_bounds__(256) void k_scores_mma(){
  __shared__ __align__(16) __nv_bfloat16 sQh[64*SQS], sQl[64*SQS];
  __shared__ __align__(16) __nv_bfloat16 sKh[64*SQS], sKl[64*SQS];
  const int tid = threadIdx.x;
  const int p = blockIdx.z, n0 = blockIdx.y*64, m0 = blockIdx.x*64;
  const __nv_bfloat16* Qh = g_qh + (size_t)p*PLANE_QV + (size_t)n0*ND;
  const __nv_bfloat16* Ql = g_ql + (size_t)p*PLANE_QV + (size_t)n0*ND;
  const __nv_bfloat16* Kh = g_kh + (size_t)p*PLANE_QV + (size_t)m0*ND;
  const __nv_bfloat16* Kl = g_kl + (size_t)p*PLANE_QV + (size_t)m0*ND;
  #pragma unroll
  for (int c0=0;c0<2;c0++){
    int c = tid + 256*c0;
    int row = c >> 3, col = (c & 7) * 8;
    *(uint4*)&sQh[row*SQS+col] = *(const uint4*)&Qh[row*64+col];
    *(uint4*)&sQl[row*SQS+col] = *(const uint4*)&Ql[row*64+col];
    *(uint4*)&sKh[row*SQS+col] = *(const uint4*)&Kh[row*64+col];
    *(uint4*)&sKl[row*SQS+col] = *(const uint4*)&Kl[row*64+col];
  }
  __syncthreads();
  const int w = tid >> 5, lane = tid & 31;
  const int ns = (w >> 1) * 16, mh = (w & 1) * 32;
  float acc[4][4] = {};
  #pragma unroll
  for (int ks=0; ks<4; ks++){
    const int k0 = ks*16;
    const int arow = ns + (lane & 15);
    const int acol = k0 + (lane >> 4) * 8;
    uint32_t ah0,ah1,ah2,ah3, al0,al1,al2,al3;
    ldm_x4(sptr(&sQh[arow*SQS + acol]), ah0,ah1,ah2,ah3);
    ldm_x4(sptr(&sQl[arow*SQS + acol]), al0,al1,al2,al3);
    SPLIT_MMA_STEP(sKh, sKl, mh, k0, lane, acc, ah0,ah1,ah2,ah3, al0,al1,al2,al3)
  }
  const int crow = n0 + ns + (lane >> 2);
  #pragma unroll
  for (int t=0;t<4;t++){
    const int ccol = m0 + mh + t*8 + (lane & 3)*2;
    size_t base = ((size_t)p<<20) + ((size_t)crow<<10) + ccol;
    *(float2*)&g_qk[base]            = make_float2(acc[t][0], acc[t][1]);
    *(float2*)&g_qk[base + (8<<10)]  = make_float2(acc[t][2], acc[t][3]);
  }
}

// ---------------- K3: fused softmax + conv/sigmoid + gumbel mask ----------------
__global__ __launch_bounds__(256) void k_smix(const float* __restrict__ cw,
                                              const float* __restrict__ cb,
                                              float* __restrict__ am_out,
                                              float* __restrict__ u_out,
                                              unsigned k0a, unsigned k0b,
                                              unsigned k1a, unsigned k1b){
  __shared__ float scw[36];
  __shared__ float scb[6];
  __shared__ float red[6][8];
  __shared__ float bcast[6];
  const int tid = threadIdx.x;
  const int wid = tid >> 5, lane = tid & 31;
  if (tid < 36) scw[tid] = cw[tid];
  if (tid < 6)  scb[tid] = cb[tid];
  const int n = blockIdx.x;
  const int b = blockIdx.y;
  float qv[6][4];
  #pragma unroll
  for (int h=0;h<6;h++){
    size_t base = ((size_t)(b*6+h) << 20) + ((size_t)n << 10) + tid;
    #pragma unroll
    for (int j=0;j<4;j++) qv[h][j] = g_qk[base + 256*j];
  }
  #pragma unroll
  for (int h=0;h<6;h++){
    float lm = fmaxf(fmaxf(qv[h][0],qv[h][1]), fmaxf(qv[h][2],qv[h][3]));
    #pragma unroll
    for (int o=16;o>0;o>>=1) lm = fmaxf(lm, __shfl_xor_sync(0xffffffffu, lm, o));
    if (lane == 0) red[h][wid] = lm;
  }
  __syncthreads();
  if (tid < 6){
    float mm = red[tid][0];
    #pragma unroll
    for (int i=1;i<8;i++) mm = fmaxf(mm, red[tid][i]);
    bcast[tid] = mm;
  }
  __syncthreads();
  float at[6][4];
  #pragma unroll
  for (int h=0;h<6;h++){
    float mr = bcast[h];
    float s = 0.f;
    #pragma unroll
    for (int j=0;j<4;j++){ at[h][j] = __expf((qv[h][j]-mr)*0.125f); s += at[h][j]; }
    #pragma unroll
    for (int o=16;o>0;o>>=1) s += __shfl_xor_sync(0xffffffffu, s, o);
    if (lane == 0) red[h][wid] = s;
  }
  __syncthreads();
  if (tid < 6){
    float ss = red[tid][0];
    #pragma unroll
    for (int i=1;i<8;i++) ss += red[tid][i];
    bcast[tid] = ss;
  }
  __syncthreads();
  #pragma unroll
  for (int h=0;h<6;h++){
    float inv = 1.0f / bcast[h];
    size_t base = ((size_t)(b*6+h) << 20) + ((size_t)n << 10) + tid;
    #pragma unroll
    for (int j=0;j<4;j++){
      at[h][j] *= inv;
      am_out[base + 256*j] = at[h][j];
    }
  }
  #pragma unroll
  for (int o=0;o<6;o++){
    #pragma unroll
    for (int j=0;j<4;j++){
      float t = scb[o];
      #pragma unroll
      for (int h=0;h<6;h++) t = fmaf(scw[o*6+h], qv[h][j], t);
      // (tanh(t)+1)/2 == sigmoid(2t); MUFU path, rel err ~2^-20
      float u = 1.0f / (1.0f + __expf(-2.0f*t));
      unsigned idx = ((unsigned)(b*6+o) << 20) | ((unsigned)n << 10) | (unsigned)(tid + 256*j);
      u_out[idx] = u;
      unsigned a0,a1,b0,b1;
      threefry2x32(k0a,k0b, 0u, idx, a0,a1);
      threefry2x32(k1a,k1b, 0u, idx, b0,b1);
      float g0 = gumbel_from_bits(a0 ^ a1);
      float g1 = gumbel_from_bits(b0 ^ b1);
      bool hard = ((1.0f - u) + g1) > (u + g0);
      float masked = hard ? at[o][j] : 0.0f;
      __nv_bfloat16 mh, ml;
      f2bf(masked, mh, ml);
      g_ah[idx] = mh;
      g_al[idx] = ml;
    }
  }
}

// ---------------- K4: attn(hi/lo) @ v(hi/lo) via mma -> bf16 hi/lo for proj ----------------
__global__ __launch_bounds__(256) void k_attnv_mma(){
  __shared__ __align__(16) __nv_bfloat16 sAh[64*SQS], sAl[64*SQS];
  __shared__ __align__(16) __nv_bfloat16 sVh[64*SQS], sVl[64*SQS];
  const int tid = threadIdx.x;
  const int p = blockIdx.y, n0 = blockIdx.x*64;
  const __nv_bfloat16* Ah = g_ah + ((((size_t)p<<10) + n0) << 10);
  const __nv_bfloat16* Al = g_al + ((((size_t)p<<10) + n0) << 10);
  const __nv_bfloat16* Vh = g_vh + (size_t)p*PLANE_QV;
  const __nv_bfloat16* Vl = g_vl + (size_t)p*PLANE_QV;
  const int w = tid >> 5, lane = tid & 31;
  const int ns = (w >> 1) * 16, dh = (w & 1) * 32;
  float acc[4][4] = {};
  const int crow = tid >> 3, ccol = (tid & 7) * 8;
  for (int mb = 0; mb < 1024; mb += 64){
    #pragma unroll
    for (int c0=0;c0<2;c0++){
      int row = crow + 32*c0;
      *(uint4*)&sAh[row*SQS+ccol] = *(const uint4*)&Ah[(size_t)row*1024 + mb + ccol];
      *(uint4*)&sAl[row*SQS+ccol] = *(const uint4*)&Al[(size_t)row*1024 + mb + ccol];
      *(uint4*)&sVh[row*SQS+ccol] = *(const uint4*)&Vh[(size_t)row*1024 + mb + ccol];
      *(uint4*)&sVl[row*SQS+ccol] = *(const uint4*)&Vl[(size_t)row*1024 + mb + ccol];
    }
    __syncthreads();
    #pragma unroll
    for (int ks=0; ks<4; ks++){
      const int k0 = ks*16;
      const int arow = ns + (lane & 15);
      const int acol = k0 + (lane >> 4) * 8;
      uint32_t ah0,ah1,ah2,ah3, al0,al1,al2,al3;
      ldm_x4(sptr(&sAh[arow*SQS + acol]), ah0,ah1,ah2,ah3);
      ldm_x4(sptr(&sAl[arow*SQS + acol]), al0,al1,al2,al3);
      SPLIT_MMA_STEP(sVh, sVl, dh, k0, lane, acc, ah0,ah1,ah2,ah3, al0,al1,al2,al3)
    }
    __syncthreads();
  }
  const int bb = p / 6, hh = p % 6;
  const int orow = n0 + ns + (lane >> 2);
  #pragma unroll
  for (int t=0;t<4;t++){
    const int ocol = hh*64 + dh + t*8 + (lane & 3)*2;
    #pragma unroll
    for (int half=0; half<2; half++){
      size_t base = (size_t)(bb*NN + orow + 8*half)*NCH + ocol;
      __nv_bfloat16 h0,l0,h1,l1;
      f2bf(acc[t][2*half+0], h0,l0);
      f2bf(acc[t][2*half+1], h1,l1);
      *(unsigned*)&g_oh[base] = packbf(h0,h1);
      *(unsigned*)&g_ol[base] = packbf(l0,l1);
    }
  }
}

// ---------------- K5: out = o @ proj_w + proj_b via mma ----------------
__global__ __launch_bounds__(256) void k_proj_mma(const float* __restrict__ bias,
                                                  float* __restrict__ out){
  __shared__ __align__(16) __nv_bfloat16 sAh[64*SQS], sAl[64*SQS];
  __shared__ __align__(16) __nv_bfloat16 sBh[64*SQS], sBl[64*SQS];
  const int tid = threadIdx.x;
  const int n0 = blockIdx.x * 64;      // 0..383
  const int m0 = blockIdx.y * 64;      // 0..4095
  const int w = tid >> 5, lane = tid & 31;
  const int ns = (w >> 1) * 16, mh = (w & 1) * 32;
  const int crow = tid >> 3, ccol = (tid & 7) * 8;
  float acc[4][4] = {};
  for (int kb = 0; kb < 384; kb += 64){
    #pragma unroll
    for (int c0=0;c0<2;c0++){
      int row = crow + 32*c0;
      *(uint4*)&sAh[row*SQS+ccol] = *(const uint4*)&g_oh[(size_t)(m0+row)*384 + kb + ccol];
      *(uint4*)&sAl[row*SQS+ccol] = *(const uint4*)&g_ol[(size_t)(m0+row)*384 + kb + ccol];
      *(uint4*)&sBh[row*SQS+ccol] = *(const uint4*)&g_pwh[(size_t)(n0+row)*384 + kb + ccol];
      *(uint4*)&sBl[row*SQS+ccol] = *(const uint4*)&g_pwl[(size_t)(n0+row)*384 + kb + ccol];
    }
    __syncthreads();
    #pragma unroll
    for (int ks=0; ks<4; ks++){
      const int k0 = ks*16;
      const int arow = ns + (lane & 15);
      const int acol = k0 + (lane >> 4) * 8;
      uint32_t ah0,ah1,ah2,ah3, al0,al1,al2,al3;
      ldm_x4(sptr(&sAh[arow*SQS + acol]), ah0,ah1,ah2,ah3);
      ldm_x4(sptr(&sAl[arow*SQS + acol]), al0,al1,al2,al3);
      SPLIT_MMA_STEP(sBh, sBl, mh, k0, lane, acc, ah0,ah1,ah2,ah3, al0,al1,al2,al3)
    }
    __syncthreads();
  }
  const int rl = m0 + ns + (lane >> 2);
  #pragma unroll
  for (int t=0;t<4;t++){
    const int col = n0 + mh + t*8 + (lane & 3)*2;
    const float b0 = bias[col], b1 = bias[col+1];
    *(float2*)&out[(size_t)rl*384 + col]     = make_float2(acc[t][0]+b0, acc[t][1]+b1);
    *(float2*)&out[(size_t)(rl+8)*384 + col] = make_float2(acc[t][2]+b0, acc[t][3]+b1);
  }
}

// ---------------- launch ----------------
extern "C" void kernel_launch(void* const* d_in, const int* in_sizes, int n_in,
                              void* d_out, int out_size){
  (void)in_sizes; (void)n_in; (void)out_size;
  const float* x      = (const float*)d_in[0];
  const float* qkv_w  = (const float*)d_in[1];
  const float* qkv_b  = (const float*)d_in[2];
  const float* proj_w = (const float*)d_in[3];
  const float* proj_b = (const float*)d_in[4];
  const float* conv_w = (const float*)d_in[5];
  const float* conv_b = (const float*)d_in[6];
  float* out      = (float*)d_out;
  float* out_attn = out + (size_t)NB*NN*NCH;          // 1,572,864
  float* out_u    = out_attn + (size_t)S_TOTAL;       // +25,165,824

  unsigned k0a,k0b,k1a,k1b;
  threefry2x32(0u, 42u, 0u, 0u, k0a, k0b);
  threefry2x32(0u, 42u, 0u, 1u, k1a, k1b);

  __nv_bfloat16 *wqh_p, *wql_p, *pwh_p, *pwl_p;
  cudaGetSymbolAddress((void**)&wqh_p, g_wqh);
  cudaGetSymbolAddress((void**)&wql_p, g_wql);
  cudaGetSymbolAddress((void**)&pwh_p, g_pwh);
  cudaGetSymbolAddress((void**)&pwl_p, g_pwl);

  k_split_x   <<<1536, 256>>>(x);
  k_tsplit    <<<dim3(36,12), dim3(32,8)>>>(qkv_w, wqh_p, wql_p, 384, 1152);
  k_tsplit    <<<dim3(12,12), dim3(32,8)>>>(proj_w, pwh_p, pwl_p, 384, 384);
  k_qkv_mma   <<<dim3(18,64),   256>>>(qkv_b);
  k_scores_mma<<<dim3(16,16,24),256>>>();
  k_smix      <<<dim3(1024,4),  256>>>(conv_w, conv_b, out_attn, out_u, k0a,k0b,k1a,k1b);
  k_attnv_mma <<<dim3(16,24),   256>>>();
  k_proj_mma  <<<dim3(6,64),    256>>>(proj_b, out);
}

// round 15
// speedup vs baseline: 1.6069x; 1.0592x over previous
#include <cuda_runtime.h>
#include <cuda_bf16.h>
#include <cstdint>

#define NB 4
#define NH 6
#define NN 1024
#define ND 64
#define NCH 384
#define NPLANES (NB*NH)            /* 24 */
#define PLANE_QV (NN*ND)           /* 65536 */
#define S_TOTAL  (25165824u)       /* B*H*N*N */

// ---------------- scratch (device globals; no allocs allowed) ----------------
__device__ __nv_bfloat16 g_xh[NB*NN*NCH];          // x split  [m][k]
__device__ __nv_bfloat16 g_xl[NB*NN*NCH];
__device__ __nv_bfloat16 g_wqh[NCH*3*NCH];         // qkv_w^T split [n][k]
__device__ __nv_bfloat16 g_wql[NCH*3*NCH];
__device__ __nv_bfloat16 g_pwh[NCH*NCH];           // proj_w^T split [n][k]
__device__ __nv_bfloat16 g_pwl[NCH*NCH];
__device__ __nv_bfloat16 g_qh[NPLANES*PLANE_QV];   // q hi  [p][n][d]
__device__ __nv_bfloat16 g_ql[NPLANES*PLANE_QV];
__device__ __nv_bfloat16 g_kh[NPLANES*PLANE_QV];   // k hi  [p][m][d]
__device__ __nv_bfloat16 g_kl[NPLANES*PLANE_QV];
__device__ __nv_bfloat16 g_vh[NPLANES*PLANE_QV];   // v hi  [p][d][n]  (TRANSPOSED)
__device__ __nv_bfloat16 g_vl[NPLANES*PLANE_QV];
__device__ float g_qk[(size_t)NPLANES*NN*NN];      // raw scores f32
__device__ __nv_bfloat16 g_ah[(size_t)NPLANES*NN*NN];  // masked attn hi [p][n][m]
__device__ __nv_bfloat16 g_al[(size_t)NPLANES*NN*NN];  // masked attn lo
__device__ __nv_bfloat16 g_oh[NB*NN*NCH];          // attn@v result split [m][k]
__device__ __nv_bfloat16 g_ol[NB*NN*NCH];

// ---------------- threefry2x32-20 (host+device) ----------------
__host__ __device__ inline unsigned rotl32(unsigned x, int r){
#ifdef __CUDA_ARCH__
  return __funnelshift_l(x, x, r);
#else
  return (x << r) | (x >> (32 - r));
#endif
}

__host__ __device__ inline void threefry2x32(unsigned k0, unsigned k1,
                                             unsigned c0, unsigned c1,
                                             unsigned &o0, unsigned &o1){
  unsigned ks0 = k0, ks1 = k1, ks2 = k0 ^ k1 ^ 0x1BD11BDAu;
  unsigned x0 = c0 + ks0, x1 = c1 + ks1;
#define TF_RND(r) { x0 += x1; x1 = rotl32(x1, r); x1 ^= x0; }
  TF_RND(13) TF_RND(15) TF_RND(26) TF_RND(6)
  x0 += ks1; x1 += ks2 + 1u;
  TF_RND(17) TF_RND(29) TF_RND(16) TF_RND(24)
  x0 += ks2; x1 += ks0 + 2u;
  TF_RND(13) TF_RND(15) TF_RND(26) TF_RND(6)
  x0 += ks0; x1 += ks1 + 3u;
  TF_RND(17) TF_RND(29) TF_RND(16) TF_RND(24)
  x0 += ks1; x1 += ks2 + 4u;
  TF_RND(13) TF_RND(15) TF_RND(26) TF_RND(6)
  x0 += ks2; x1 += ks0 + 5u;
#undef TF_RND
  o0 = x0; o1 = x1;
}

__device__ __forceinline__ float gumbel_from_bits(unsigned bits){
  const float tiny = 1.17549435e-38f;
  float f = __uint_as_float((bits >> 9) | 0x3f800000u) - 1.0f;
  float r = fmaxf(tiny, f + tiny);
  return -__logf(-__logf(r));
}

// ---------------- bf16 split + mma + cp.async helpers ----------------
__device__ __forceinline__ void f2bf(float x, __nv_bfloat16 &h, __nv_bfloat16 &l){
  h = __float2bfloat16(x);
  l = __float2bfloat16(x - __bfloat162float(h));
}
__device__ __forceinline__ unsigned packbf(__nv_bfloat16 a, __nv_bfloat16 b){
  unsigned short ua = __bfloat16_as_ushort(a), ub = __bfloat16_as_ushort(b);
  return (unsigned)ua | ((unsigned)ub << 16);
}

__device__ __forceinline__ uint32_t sptr(const void* p){
  return (uint32_t)__cvta_generic_to_shared(p);
}

__device__ __forceinline__ void cp16(uint32_t saddr, const void* gaddr){
  asm volatile("cp.async.cg.shared.global [%0], [%1], 16;\n" :: "r"(saddr), "l"(gaddr));
}
__device__ __forceinline__ void cp_commit(){
  asm volatile("cp.async.commit_group;\n" ::: "memory");
}
template<int N> __device__ __forceinline__ void cp_wait(){
  asm volatile("cp.async.wait_group %0;\n" :: "n"(N) : "memory");
}

__device__ __forceinline__ void ldm_x4(uint32_t a, uint32_t &r0, uint32_t &r1,
                                       uint32_t &r2, uint32_t &r3){
  asm volatile("ldmatrix.sync.aligned.m8n8.x4.shared.b16 {%0,%1,%2,%3}, [%4];"
    : "=r"(r0),"=r"(r1),"=r"(r2),"=r"(r3) : "r"(a));
}
__device__ __forceinline__ void mma16816(float &c0,float &c1,float &c2,float &c3,
    uint32_t a0,uint32_t a1,uint32_t a2,uint32_t a3, uint32_t b0,uint32_t b1){
  asm volatile("mma.sync.aligned.m16n8k16.row.col.f32.bf16.bf16.f32 "
    "{%0,%1,%2,%3}, {%4,%5,%6,%7}, {%8,%9}, {%0,%1,%2,%3};"
    : "+f"(c0),"+f"(c1),"+f"(c2),"+f"(c3)
    : "r"(a0),"r"(a1),"r"(a2),"r"(a3),"r"(b0),"r"(b1));
}

#define SQS 72

// Inner split-MMA step over one 64-col B strip (B via x4 ldmatrix, 2 n-octets/instr).
#define SPLIT_MMA_STEP(sBh_, sBl_, mh_, k0_, lane_, acc_, AH0,AH1,AH2,AH3, AL0,AL1,AL2,AL3) \
  { \
    const int _bq = (((lane_) >> 3) & 1) * 8; \
    const int _br = (((lane_) >> 4) & 1) * 8 + ((lane_) & 7); \
    _Pragma("unroll") \
    for (int _tp = 0; _tp < 2; _tp++){ \
      const int _row = (mh_) + _tp*16 + _br; \
      uint32_t _bh0,_bh1,_bh2,_bh3, _bl0,_bl1,_bl2,_bl3; \
      ldm_x4(sptr(&(sBh_)[_row*SQS + (k0_) + _bq]), _bh0,_bh1,_bh2,_bh3); \
      ldm_x4(sptr(&(sBl_)[_row*SQS + (k0_) + _bq]), _bl0,_bl1,_bl2,_bl3); \
      const int _t0 = _tp*2, _t1 = _tp*2 + 1; \
      mma16816(acc_[_t0][0],acc_[_t0][1],acc_[_t0][2],acc_[_t0][3], AH0,AH1,AH2,AH3, _bh0,_bh1); \
      mma16816(acc_[_t0][0],acc_[_t0][1],acc_[_t0][2],acc_[_t0][3], AH0,AH1,AH2,AH3, _bl0,_bl1); \
      mma16816(acc_[_t0][0],acc_[_t0][1],acc_[_t0][2],acc_[_t0][3], AL0,AL1,AL2,AL3, _bh0,_bh1); \
      mma16816(acc_[_t1][0],acc_[_t1][1],acc_[_t1][2],acc_[_t1][3], AH0,AH1,AH2,AH3, _bh2,_bh3); \
      mma16816(acc_[_t1][0],acc_[_t1][1],acc_[_t1][2],acc_[_t1][3], AH0,AH1,AH2,AH3, _bl2,_bl3); \
      mma16816(acc_[_t1][0],acc_[_t1][1],acc_[_t1][2],acc_[_t1][3], AL0,AL1,AL2,AL3, _bh2,_bh3); \
    } \
  }

// ---------------- K0a: split x into bf16 hi/lo ----------------
__global__ __launch_bounds__(256) void k_split_x(const float* __restrict__ X){
  const int i = blockIdx.x*256 + threadIdx.x;          // 393216 float4 groups
  float4 v = ((const float4*)X)[i];
  __nv_bfloat16 h0,l0,h1,l1,h2,l2,h3,l3;
  f2bf(v.x,h0,l0); f2bf(v.y,h1,l1); f2bf(v.z,h2,l2); f2bf(v.w,h3,l3);
  ((uint2*)g_xh)[i] = make_uint2(packbf(h0,h1), packbf(h2,h3));
  ((uint2*)g_xl)[i] = make_uint2(packbf(l0,l1), packbf(l2,l3));
}

// ---------------- K0b: transpose-split weight [R][C] f32 -> [C][R] bf16 hi/lo ----------------
__global__ void k_tsplit(const float* __restrict__ W,
                         __nv_bfloat16* __restrict__ oh,
                         __nv_bfloat16* __restrict__ ol,
                         int R, int C){
  __shared__ float t[32][33];
  const int tx = threadIdx.x, ty = threadIdx.y;       // 32 x 8
  const int c0 = blockIdx.x*32, r0 = blockIdx.y*32;
  #pragma unroll
  for (int j=0;j<4;j++) t[ty+8*j][tx] = W[(size_t)(r0+ty+8*j)*C + c0 + tx];
  __syncthreads();
  #pragma unroll
  for (int j=0;j<4;j++){
    float v = t[tx][ty+8*j];
    __nv_bfloat16 h,l; f2bf(v,h,l);
    size_t o = (size_t)(c0+ty+8*j)*R + r0 + tx;
    oh[o] = h; ol[o] = l;
  }
}

// ---------------- K1: qkv = x @ W + b via mma, scatter to q/k/v hi-lo ----------------
__global__ __launch_bounds__(256,3) void k_qkv_mma(const float* __restrict__ bias){
  __shared__ __align__(16) __nv_bfloat16 sAh[64*SQS], sAl[64*SQS];
  __shared__ __align__(16) __nv_bfloat16 sBh[64*SQS], sBl[64*SQS];
  __shared__ __align__(16) float sT[64][65];
  const int tid = threadIdx.x;
  const int n0 = blockIdx.x * 64;      // 0..1151
  const int m0 = blockIdx.y * 64;      // 0..4095
  const int w = tid >> 5, lane = tid & 31;
  const int ns = (w >> 1) * 16, mh = (w & 1) * 32;
  const int crow = tid >> 3, ccol = (tid & 7) * 8;
  float acc[4][4] = {};
  for (int kb = 0; kb < 384; kb += 64){
    #pragma unroll
    for (int c0=0;c0<2;c0++){
      int row = crow + 32*c0;
      cp16(sptr(&sAh[row*SQS+ccol]), &g_xh[(size_t)(m0+row)*384 + kb + ccol]);
      cp16(sptr(&sAl[row*SQS+ccol]), &g_xl[(size_t)(m0+row)*384 + kb + ccol]);
      cp16(sptr(&sBh[row*SQS+ccol]), &g_wqh[(size_t)(n0+row)*384 + kb + ccol]);
      cp16(sptr(&sBl[row*SQS+ccol]), &g_wql[(size_t)(n0+row)*384 + kb + ccol]);
    }
    cp_commit(); cp_wait<0>();
    __syncthreads();
    #pragma unroll
    for (int ks=0; ks<4; ks++){
      const int k0 = ks*16;
      const int arow = ns + (lane & 15);
      const int acol = k0 + (lane >> 4) * 8;
      uint32_t ah0,ah1,ah2,ah3, al0,al1,al2,al3;
      ldm_x4(sptr(&sAh[arow*SQS + acol]), ah0,ah1,ah2,ah3);
      ldm_x4(sptr(&sAl[arow*SQS + acol]), al0,al1,al2,al3);
      SPLIT_MMA_STEP(sBh, sBl, mh, k0, lane, acc, ah0,ah1,ah2,ah3, al0,al1,al2,al3)
    }
    __syncthreads();
  }
  const int s = n0 / 384;
  const int h = (n0 % 384) / 64;
  if (s < 2){
    __nv_bfloat16* dh = s ? g_kh : g_qh;
    __nv_bfloat16* dl = s ? g_kl : g_ql;
    const int rl = m0 + ns + (lane >> 2);
    #pragma unroll
    for (int t=0;t<4;t++){
      const int col = mh + t*8 + (lane & 3)*2;
      const float b0 = bias[n0+col], b1 = bias[n0+col+1];
      #pragma unroll
      for (int half=0; half<2; half++){
        int r = rl + 8*half;
        int bb = r >> 10, nn = r & 1023;
        size_t base = ((size_t)(bb*NH + h)*NN + nn)*ND + col;
        __nv_bfloat16 h0,l0,h1,l1;
        f2bf(acc[t][2*half+0]+b0, h0,l0);
        f2bf(acc[t][2*half+1]+b1, h1,l1);
        *(unsigned*)&dh[base] = packbf(h0,h1);
        *(unsigned*)&dl[base] = packbf(l0,l1);
      }
    }
  } else {
    const int rl = ns + (lane >> 2);
    #pragma unroll
    for (int t=0;t<4;t++){
      const int col = mh + t*8 + (lane & 3)*2;
      const float b0 = bias[n0+col], b1 = bias[n0+col+1];
      sT[col  ][rl  ] = acc[t][0]+b0;
      sT[col+1][rl  ] = acc[t][1]+b1;
      sT[col  ][rl+8] = acc[t][2]+b0;
      sT[col+1][rl+8] = acc[t][3]+b1;
    }
    __syncthreads();
    const int dloc = tid >> 2;
    const int nch  = (tid & 3) * 16;
    const int bb = m0 >> 10;
    const int nb = (m0 & 1023) + nch;
    size_t base = ((size_t)(bb*NH + h))*PLANE_QV + (size_t)dloc*NN + nb;
    union { __nv_bfloat16 q[16]; uint4 u[2]; } ph, pl;
    #pragma unroll
    for (int kk=0;kk<16;kk++) f2bf(sT[dloc][nch+kk], ph.q[kk], pl.q[kk]);
    *(uint4*)&g_vh[base]   = ph.u[0];
    *(uint4*)&g_vh[base+8] = ph.u[1];
    *(uint4*)&g_vl[base]   = pl.u[0];
    *(uint4*)&g_vl[base+8] = pl.u[1];
  }
}

// ---------------- K2: scores via mma.sync bf16 split ----------------
__global__ __launch_bounds__(256,3) void k_scores_mma(){
  __shared__ __align__(16) __nv_bfloat16 sQh[64*SQS], sQl[64*SQS];
  __shared__ __align__(16) __nv_bfloat16 sKh[64*SQS], sKl[64*SQS];
  const int tid = threadIdx.x;
  const int p = blockIdx.z, n0 = blockIdx.y*64, m0 = blockIdx.x*64;
  const __nv_bfloat16* Qh = g_qh + (size_t)p*PLANE_QV + (size_t)n0*ND;
  const __nv_bfloat16* Ql = g_ql + (size_t)p*PLANE_QV + (size_t)n0*ND;
  const __nv_bfloat16* Kh = g_kh + (size_t)p*PLANE_QV + (size_t)m0*ND;
  const __nv_bfloat16* Kl = g_kl + (size_t)p*PLANE_QV + (size_t)m0*ND;
  #pragma unroll
  for (int c0=0;c0<2;c0++){
    int c = tid + 256*c0;
    int row = c >> 3, col = (c & 7) * 8;
    cp16(sptr(&sQh[row*SQS+col]), &Qh[row*64+col]);
    cp16(sptr(&sQl[row*SQS+col]), &Ql[row*64+col]);
    cp16(sptr(&sKh[row*SQS+col]), &Kh[row*64+col]);
    cp16(sptr(&sKl[row*SQS+col]), &Kl[row*64+col]);
  }
  cp_commit(); cp_wait<0>();
  __syncthreads();
  const int w = tid >> 5, lane = tid & 31;
  const int ns = (w >> 1) * 16, mh = (w & 1) * 32;
  float acc[4][4] = {};
  #pragma unroll
  for (int ks=0; ks<4; ks++){
    const int k0 = ks*16;
    const int arow = ns + (lane & 15);
    const int acol = k0 + (lane >> 4) * 8;
    uint32_t ah0,ah1,ah2,ah3, al0,al1,al2,al3;
    ldm_x4(sptr(&sQh[arow*SQS + acol]), ah0,ah1,ah2,ah3);
    ldm_x4(sptr(&sQl[arow*SQS + acol]), al0,al1,al2,al3);
    SPLIT_MMA_STEP(sKh, sKl, mh, k0, lane, acc, ah0,ah1,ah2,ah3, al0,al1,al2,al3)
  }
  const int crow = n0 + ns + (lane >> 2);
  #pragma unroll
  for (int t=0;t<4;t++){
    const int ccol = m0 + mh + t*8 + (lane & 3)*2;
    size_t base = ((size_t)p<<20) + ((size_t)crow<<10) + ccol;
    *(float2*)&g_qk[base]            = make_float2(acc[t][0], acc[t][1]);
    *(float2*)&g_qk[base + (8<<10)]  = make_float2(acc[t][2], acc[t][3]);
  }
}

// ---------------- K3: fused softmax + conv/sigmoid + gumbel mask ----------------
__global__ __launch_bounds__(256) void k_smix(const float* __restrict__ cw,
                                              const float* __restrict__ cb,
                                              float* __restrict__ am_out,
                                              float* __restrict__ u_out,
                                              unsigned k0a, unsigned k0b,
                                              unsigned k1a, unsigned k1b){
  __shared__ float scw[36];
  __shared__ float scb[6];
  __shared__ float red[6][8];
  __shared__ float bcast[6];
  const int tid = threadIdx.x;
  const int wid = tid >> 5, lane = tid & 31;
  if (tid < 36) scw[tid] = cw[tid];
  if (tid < 6)  scb[tid] = cb[tid];
  const int n = blockIdx.x;
  const int b = blockIdx.y;
  float qv[6][4];
  #pragma unroll
  for (int h=0;h<6;h++){
    size_t base = ((size_t)(b*6+h) << 20) + ((size_t)n << 10) + tid;
    #pragma unroll
    for (int j=0;j<4;j++) qv[h][j] = g_qk[base + 256*j];
  }
  #pragma unroll
  for (int h=0;h<6;h++){
    float lm = fmaxf(fmaxf(qv[h][0],qv[h][1]), fmaxf(qv[h][2],qv[h][3]));
    #pragma unroll
    for (int o=16;o>0;o>>=1) lm = fmaxf(lm, __shfl_xor_sync(0xffffffffu, lm, o));
    if (lane == 0) red[h][wid] = lm;
  }
  __syncthreads();
  if (tid < 6){
    float mm = red[tid][0];
    #pragma unroll
    for (int i=1;i<8;i++) mm = fmaxf(mm, red[tid][i]);
    bcast[tid] = mm;
  }
  __syncthreads();
  float at[6][4];
  #pragma unroll
  for (int h=0;h<6;h++){
    float mr = bcast[h];
    float s = 0.f;
    #pragma unroll
    for (int j=0;j<4;j++){ at[h][j] = __expf((qv[h][j]-mr)*0.125f); s += at[h][j]; }
    #pragma unroll
    for (int o=16;o>0;o>>=1) s += __shfl_xor_sync(0xffffffffu, s, o);
    if (lane == 0) red[h][wid] = s;
  }
  __syncthreads();
  if (tid < 6){
    float ss = red[tid][0];
    #pragma unroll
    for (int i=1;i<8;i++) ss += red[tid][i];
    bcast[tid] = ss;
  }
  __syncthreads();
  #pragma unroll
  for (int h=0;h<6;h++){
    float inv = 1.0f / bcast[h];
    size_t base = ((size_t)(b*6+h) << 20) + ((size_t)n << 10) + tid;
    #pragma unroll
    for (int j=0;j<4;j++){
      at[h][j] *= inv;
      am_out[base + 256*j] = at[h][j];
    }
  }
  #pragma unroll
  for (int o=0;o<6;o++){
    #pragma unroll
    for (int j=0;j<4;j++){
      float t = scb[o];
      #pragma unroll
      for (int h=0;h<6;h++) t = fmaf(scw[o*6+h], qv[h][j], t);
      // (tanh(t)+1)/2 == sigmoid(2t); MUFU path, rel err ~2^-20
      float u = 1.0f / (1.0f + __expf(-2.0f*t));
      unsigned idx = ((unsigned)(b*6+o) << 20) | ((unsigned)n << 10) | (unsigned)(tid + 256*j);
      u_out[idx] = u;
      unsigned a0,a1,b0,b1;
      threefry2x32(k0a,k0b, 0u, idx, a0,a1);
      threefry2x32(k1a,k1b, 0u, idx, b0,b1);
      float g0 = gumbel_from_bits(a0 ^ a1);
      float g1 = gumbel_from_bits(b0 ^ b1);
      bool hard = ((1.0f - u) + g1) > (u + g0);
      float masked = hard ? at[o][j] : 0.0f;
      __nv_bfloat16 mh, ml;
      f2bf(masked, mh, ml);
      g_ah[idx] = mh;
      g_al[idx] = ml;
    }
  }
}

// ---------------- K4: attn(hi/lo) @ v(hi/lo) via mma, double-buffered ----------------
#define ATTNV_ISSUE(mb_, buf_) \
  { \
    _Pragma("unroll") \
    for (int _c0=0;_c0<2;_c0++){ \
      int _row = crow + 32*_c0; \
      cp16(sptr(&sAh[buf_][_row*SQS+ccol]), &Ah[(size_t)_row*1024 + (mb_) + ccol]); \
      cp16(sptr(&sAl[buf_][_row*SQS+ccol]), &Al[(size_t)_row*1024 + (mb_) + ccol]); \
      cp16(sptr(&sVh[buf_][_row*SQS+ccol]), &Vh[(size_t)_row*1024 + (mb_) + ccol]); \
      cp16(sptr(&sVl[buf_][_row*SQS+ccol]), &Vl[(size_t)_row*1024 + (mb_) + ccol]); \
    } \
    cp_commit(); \
  }

__global__ __launch_bounds__(256,3) void k_attnv_mma(){
  __shared__ __align__(16) __nv_bfloat16 sAh[2][64*SQS], sAl[2][64*SQS];
  __shared__ __align__(16) __nv_bfloat16 sVh[2][64*SQS], sVl[2][64*SQS];
  const int tid = threadIdx.x;
  const int p = blockIdx.y, n0 = blockIdx.x*64;
  const __nv_bfloat16* Ah = g_ah + ((((size_t)p<<10) + n0) << 10);
  const __nv_bfloat16* Al = g_al + ((((size_t)p<<10) + n0) << 10);
  const __nv_bfloat16* Vh = g_vh + (size_t)p*PLANE_QV;
  const __nv_bfloat16* Vl = g_vl + (size_t)p*PLANE_QV;
  const int w = tid >> 5, lane = tid & 31;
  const int ns = (w >> 1) * 16, dh = (w & 1) * 32;
  float acc[4][4] = {};
  const int crow = tid >> 3, ccol = (tid & 7) * 8;
  ATTNV_ISSUE(0, 0)
  for (int i = 0; i < 16; i++){
    const int buf = i & 1;
    if (i < 15){ ATTNV_ISSUE((i+1)*64, buf^1) cp_wait<1>(); }
    else       { cp_wait<0>(); }
    __syncthreads();
    #pragma unroll
    for (int ks=0; ks<4; ks++){
      const int k0 = ks*16;
      const int arow = ns + (lane & 15);
      const int acol = k0 + (lane >> 4) * 8;
      uint32_t ah0,ah1,ah2,ah3, al0,al1,al2,al3;
      ldm_x4(sptr(&sAh[buf][arow*SQS + acol]), ah0,ah1,ah2,ah3);
      ldm_x4(sptr(&sAl[buf][arow*SQS + acol]), al0,al1,al2,al3);
      SPLIT_MMA_STEP(sVh[buf], sVl[buf], dh, k0, lane, acc, ah0,ah1,ah2,ah3, al0,al1,al2,al3)
    }
    __syncthreads();
  }
  const int bb = p / 6, hh = p % 6;
  const int orow = n0 + ns + (lane >> 2);
  #pragma unroll
  for (int t=0;t<4;t++){
    const int ocol = hh*64 + dh + t*8 + (lane & 3)*2;
    #pragma unroll
    for (int half=0; half<2; half++){
      size_t base = (size_t)(bb*NN + orow + 8*half)*NCH + ocol;
      __nv_bfloat16 h0,l0,h1,l1;
      f2bf(acc[t][2*half+0], h0,l0);
      f2bf(acc[t][2*half+1], h1,l1);
      *(unsigned*)&g_oh[base] = packbf(h0,h1);
      *(unsigned*)&g_ol[base] = packbf(l0,l1);
    }
  }
}

// ---------------- K5: out = o @ proj_w + proj_b via mma ----------------
__global__ __launch_bounds__(256,3) void k_proj_mma(const float* __restrict__ bias,
                                                    float* __restrict__ out){
  __shared__ __align__(16) __nv_bfloat16 sAh[64*SQS], sAl[64*SQS];
  __shared__ __align__(16) __nv_bfloat16 sBh[64*SQS], sBl[64*SQS];
  const int tid = threadIdx.x;
  const int n0 = blockIdx.x * 64;      // 0..383
  const int m0 = blockIdx.y * 64;      // 0..4095
  const int w = tid >> 5, lane = tid & 31;
  const int ns = (w >> 1) * 16, mh = (w & 1) * 32;
  const int crow = tid >> 3, ccol = (tid & 7) * 8;
  float acc[4][4] = {};
  for (int kb = 0; kb < 384; kb += 64){
    #pragma unroll
    for (int c0=0;c0<2;c0++){
      int row = crow + 32*c0;
      cp16(sptr(&sAh[row*SQS+ccol]), &g_oh[(size_t)(m0+row)*384 + kb + ccol]);
      cp16(sptr(&sAl[row*SQS+ccol]), &g_ol[(size_t)(m0+row)*384 + kb + ccol]);
      cp16(sptr(&sBh[row*SQS+ccol]), &g_pwh[(size_t)(n0+row)*384 + kb + ccol]);
      cp16(sptr(&sBl[row*SQS+ccol]), &g_pwl[(size_t)(n0+row)*384 + kb + ccol]);
    }
    cp_commit(); cp_wait<0>();
    __syncthreads();
    #pragma unroll
    for (int ks=0; ks<4; ks++){
      const int k0 = ks*16;
      const int arow = ns + (lane & 15);
      const int acol = k0 + (lane >> 4) * 8;
      uint32_t ah0,ah1,ah2,ah3, al0,al1,al2,al3;
      ldm_x4(sptr(&sAh[arow*SQS + acol]), ah0,ah1,ah2,ah3);
      ldm_x4(sptr(&sAl[arow*SQS + acol]), al0,al1,al2,al3);
      SPLIT_MMA_STEP(sBh, sBl, mh, k0, lane, acc, ah0,ah1,ah2,ah3, al0,al1,al2,al3)
    }
    __syncthreads();
  }
  const int rl = m0 + ns + (lane >> 2);
  #pragma unroll
  for (int t=0;t<4;t++){
    const int col = n0 + mh + t*8 + (lane & 3)*2;
    const float b0 = bias[col], b1 = bias[col+1];
    *(float2*)&out[(size_t)rl*384 + col]     = make_float2(acc[t][0]+b0, acc[t][1]+b1);
    *(float2*)&out[(size_t)(rl+8)*384 + col] = make_float2(acc[t][2]+b0, acc[t][3]+b1);
  }
}

// ---------------- launch ----------------
extern "C" void kernel_launch(void* const* d_in, const int* in_sizes, int n_in,
                              void* d_out, int out_size){
  (void)in_sizes; (void)n_in; (void)out_size;
  const float* x      = (const float*)d_in[0];
  const float* qkv_w  = (const float*)d_in[1];
  const float* qkv_b  = (const float*)d_in[2];
  const float* proj_w = (const float*)d_in[3];
  const float* proj_b = (const float*)d_in[4];
  const float* conv_w = (const float*)d_in[5];
  const float* conv_b = (const float*)d_in[6];
  float* out      = (float*)d_out;
  float* out_attn = out + (size_t)NB*NN*NCH;          // 1,572,864
  float* out_u    = out_attn + (size_t)S_TOTAL;       // +25,165,824

  unsigned k0a,k0b,k1a,k1b;
  threefry2x32(0u, 42u, 0u, 0u, k0a, k0b);
  threefry2x32(0u, 42u, 0u, 1u, k1a, k1b);

  __nv_bfloat16 *wqh_p, *wql_p, *pwh_p, *pwl_p;
  cudaGetSymbolAddress((void**)&wqh_p, g_wqh);
  cudaGetSymbolAddress((void**)&wql_p, g_wql);
  cudaGetSymbolAddress((void**)&pwh_p, g_pwh);
  cudaGetSymbolAddress((void**)&pwl_p, g_pwl);

  k_split_x   <<<1536, 256>>>(x);
  k_tsplit    <<<dim3(36,12), dim3(32,8)>>>(qkv_w, wqh_p, wql_p, 384, 1152);
  k_tsplit    <<<dim3(12,12), dim3(32,8)>>>(proj_w, pwh_p, pwl_p, 384, 384);
  k_qkv_mma   <<<dim3(18,64),   256>>>(qkv_b);
  k_scores_mma<<<dim3(16,16,24),256>>>();
  k_smix      <<<dim3(1024,4),  256>>>(conv_w, conv_b, out_attn, out_u, k0a,k0b,k1a,k1b);
  k_attnv_mma <<<dim3(16,24),   256>>>();
  k_proj_mma  <<<dim3(6,64),    256>>>(proj_b, out);
}